// round 3
// baseline (speedup 1.0000x reference)
#include <cuda_runtime.h>
#include <cuda_bf16.h>

// SENet gating, warp-pipelined version.
// Each warp grid-strides over 6-row tiles with TWO smem buffers:
// issue cp.async for tile t+1, wait for tile t (already in flight one full
// iteration), process tile t. Warps never expose cold DRAM latency after
// the prologue; the kernel runs at whatever HBM delivers.

#define NFEAT 188
#define NF4   47
#define R     6                    // rows per warp-tile
#define TILE_F  (R * NFEAT)        // 1128 floats = 4512 B
#define WARPS 4
#define NTHREADS (WARPS * 32)
#define GRID_BLOCKS 608            // 4 blocks/SM floor on 152 SMs

// packed segment ids for the 4 features of each float4 position (0..46)
__device__ __constant__ unsigned int c_stab[47] = {
    0x00000000u,0x00000000u,0x00000000u,0x00000000u,0x00000000u,
    0x01010101u,0x02020101u,0x02020202u,0x02020202u,0x02020202u,
    0x02020202u,0x03020202u,0x03030303u,0x03030303u,0x03030303u,
    0x03030303u,0x04030303u,0x04040404u,0x05050504u,0x05050505u,
    0x05050505u,0x05050505u,0x05050505u,0x06060505u,0x06060606u,
    0x06060606u,0x06060606u,0x06060606u,0x07070606u,0x07070707u,
    0x08080808u,0x08080808u,0x08080808u,0x08080808u,0x08080808u,
    0x09090908u,0x09090909u,0x09090909u,0x09090909u,0x09090909u,
    0x0A0A0A09u,0x0B0A0A0Au,0x0B0B0B0Bu,0x0B0B0B0Bu,0x0B0B0B0Bu,
    0x0B0B0B0Bu,0x0B0B0B0Bu
};

__global__ __launch_bounds__(NTHREADS, 5)
void senet_kernel(const float* __restrict__ x,
                  const float* __restrict__ W1,   // [3,12]
                  const float* __restrict__ b1,   // [3]
                  const float* __restrict__ W2,   // [12,3]
                  const float* __restrict__ b2,   // [12]
                  float* __restrict__ out,
                  int B, int T)                   // T = ceil(B/R) tiles
{
    __shared__ __align__(16) float sx[WARPS][2][TILE_F];   // 36096 B
    __shared__ float        smeans[WARPS][R][12];
    __shared__ float        sgates[WARPS][R][13];
    __shared__ float        sw[88];          // W1|b1|W2|b2 = 87 floats
    __shared__ unsigned int sstab[47];

    const int lane = threadIdx.x & 31;
    const int w    = threadIdx.x >> 5;

    // each warp redundantly writes the shared tables (identical values ->
    // benign races; own-warp program order + syncwarp makes them visible)
    for (int j = lane; j < 47; j += 32) sstab[j] = c_stab[j];
    for (int j = lane; j < 87; j += 32) {
        float v;
        if      (j < 36) v = __ldg(W1 + j);
        else if (j < 39) v = __ldg(b1 + (j - 36));
        else if (j < 75) v = __ldg(W2 + (j - 39));
        else             v = __ldg(b2 + (j - 75));
        sw[j] = v;
    }
    __syncwarp();

    const int gw  = blockIdx.x * WARPS + w;
    const int TWn = gridDim.x * WARPS;
    int t = gw;
    if (t >= T) return;

    // ---- issue loads for one tile into buffer buf ----
    auto issue = [&](int tile, int buf) {
        int rows = B - tile * R;
        if (rows > R) rows = R;
        const int n4 = rows * NF4;
        const float4* g = (const float4*)(x + (long long)tile * TILE_F);
        unsigned int sb = (unsigned int)__cvta_generic_to_shared(&sx[w][buf][0]);
        #pragma unroll 3
        for (int i = lane; i < n4; i += 32) {
            asm volatile("cp.async.cg.shared.global [%0], [%1], 16;\n"
                         :: "r"(sb + i * 16), "l"(g + i) : "memory");
        }
        asm volatile("cp.async.commit_group;\n" ::: "memory");
    };

    // ---- process one resident tile ----
    auto process = [&](int tile, int buf) {
        int rows = B - tile * R;
        if (rows > R) rows = R;
        const int n4 = rows * NF4;
        const float* sxw = &sx[w][buf][0];

        // segment sums: lane = (row rq, quarter sq); pattern (20,6,21) x 4
        {
            const int rq = lane >> 2;
            const int sq = lane & 3;
            if (rq < rows) {
                const float* xr = sxw + rq * NFEAT + sq * 47;
                float a0 = 0.f, a1 = 0.f, a2 = 0.f;
                #pragma unroll
                for (int j = 0;  j < 20; ++j) a0 += xr[j];
                #pragma unroll
                for (int j = 20; j < 26; ++j) a1 += xr[j];
                #pragma unroll
                for (int j = 26; j < 47; ++j) a2 += xr[j];
                smeans[w][rq][3 * sq + 0] = a0 * (1.f / 20.f);
                smeans[w][rq][3 * sq + 1] = a1 * (1.f / 6.f);
                smeans[w][rq][3 * sq + 2] = a2 * (1.f / 21.f);
            }
        }
        __syncwarp();

        // tiny MLP 12 -> 3(relu) -> 12(sigmoid), one lane per row
        if (lane < rows) {
            float m[12];
            #pragma unroll
            for (int k = 0; k < 12; ++k) m[k] = smeans[w][lane][k];
            float h[3];
            #pragma unroll
            for (int j = 0; j < 3; ++j) {
                float a = sw[36 + j];
                #pragma unroll
                for (int k = 0; k < 12; ++k) a += m[k] * sw[j * 12 + k];
                h[j] = fmaxf(a, 0.f);
            }
            #pragma unroll
            for (int s = 0; s < 12; ++s) {
                float a = sw[75 + s];
                #pragma unroll
                for (int j = 0; j < 3; ++j) a += h[j] * sw[39 + s * 3 + j];
                sgates[w][lane][s] = __fdividef(1.f, 1.f + __expf(-a));
            }
        }
        __syncwarp();

        // gate multiply + coalesced streaming store
        float4* gout = (float4*)(out + (long long)tile * TILE_F);
        const float4* sxw4 = (const float4*)sxw;
        #pragma unroll 3
        for (int i = lane; i < n4; i += 32) {
            const int row = i / NF4;
            const int p   = i - row * NF4;
            const unsigned int sid = sstab[p];
            const float* gr = sgates[w][row];
            float4 v = sxw4[i];
            v.x *= gr[sid         & 255];
            v.y *= gr[(sid >> 8)  & 255];
            v.z *= gr[(sid >> 16) & 255];
            v.w *= gr[ sid >> 24       ];
            __stcs(&gout[i], v);
        }
    };

    // ---- pipelined main loop ----
    issue(t, 0);
    int nt  = t + TWn;
    int buf = 0;
    while (true) {
        if (nt < T) {
            issue(nt, buf ^ 1);
            asm volatile("cp.async.wait_group 1;\n" ::: "memory");
        } else {
            asm volatile("cp.async.wait_group 0;\n" ::: "memory");
        }
        __syncwarp();
        process(t, buf);
        if (nt >= T) break;
        t   = nt;
        nt += TWn;
        buf ^= 1;
    }
}

extern "C" void kernel_launch(void* const* d_in, const int* in_sizes, int n_in,
                              void* d_out, int out_size)
{
    const float* x  = (const float*)d_in[0];
    const float* W1 = (const float*)d_in[1];
    const float* b1 = (const float*)d_in[2];
    const float* W2 = (const float*)d_in[3];
    const float* b2 = (const float*)d_in[4];
    float* out = (float*)d_out;

    const int B = in_sizes[0] / NFEAT;
    const int T = (B + R - 1) / R;
    int grid = GRID_BLOCKS;
    if (T < grid * WARPS) grid = (T + WARPS - 1) / WARPS;
    senet_kernel<<<grid, NTHREADS>>>(x, W1, b1, W2, b2, out, B, T);
}

// round 4
// speedup vs baseline: 1.1457x; 1.1457x over previous
#include <cuda_runtime.h>
#include <cuda_bf16.h>

// SENet gating, warp-synchronous (R2 shape) + occupancy push.
// Each WARP independently handles 6 rows (6 x 188 f32 = 4512 B tile):
//   1. cp.async.cg (L1-bypass) gmem -> smem, coalesced float4
//   2. segment sums: lane (row=lane/4, quarter=lane&3) sums its contiguous
//      47-float slice (segment pattern (20,6,21) x 4) -- balanced,
//      fully unrolled, bank-conflict-free
//   3. MLP 12->3->12 (relu, sigmoid), one lane per row
//   4. gate-multiply from smem + coalesced float4 streaming store
// No __syncthreads; DRAM latency hidden by ~40-48 resident warps/SM.

#define NFEAT 188
#define NF4   47
#define R     6                 // rows per warp
#define WARPS 4
#define NTHREADS (WARPS * 32)   // 128

// packed segment ids for the 4 features of each float4 position (0..46)
__device__ __constant__ unsigned int c_stab[47] = {
    0x00000000u,0x00000000u,0x00000000u,0x00000000u,0x00000000u,
    0x01010101u,0x02020101u,0x02020202u,0x02020202u,0x02020202u,
    0x02020202u,0x03020202u,0x03030303u,0x03030303u,0x03030303u,
    0x03030303u,0x04030303u,0x04040404u,0x05050504u,0x05050505u,
    0x05050505u,0x05050505u,0x05050505u,0x06060505u,0x06060606u,
    0x06060606u,0x06060606u,0x06060606u,0x07070606u,0x07070707u,
    0x08080808u,0x08080808u,0x08080808u,0x08080808u,0x08080808u,
    0x09090908u,0x09090909u,0x09090909u,0x09090909u,0x09090909u,
    0x0A0A0A09u,0x0B0A0A0Au,0x0B0B0B0Bu,0x0B0B0B0Bu,0x0B0B0B0Bu,
    0x0B0B0B0Bu,0x0B0B0B0Bu
};

__global__ __launch_bounds__(NTHREADS, 10)
void senet_kernel(const float* __restrict__ x,
                  const float* __restrict__ W1,   // [3,12]
                  const float* __restrict__ b1,   // [3]
                  const float* __restrict__ W2,   // [12,3]
                  const float* __restrict__ b2,   // [12]
                  float* __restrict__ out,
                  int B)
{
    __shared__ __align__(16) float sx[WARPS * R * NFEAT];  // 18048 B
    __shared__ float        smeans[WARPS][R][12];
    __shared__ float        sgates[WARPS][R][13];          // pad vs banks
    __shared__ unsigned int sstab[47];

    const int lane = threadIdx.x & 31;
    const int w    = threadIdx.x >> 5;

    const long long row0 = (long long)blockIdx.x * (WARPS * R) + w * R;
    int rows = B - (int)row0;
    if (rows <= 0) return;                  // warp-uniform exit
    if (rows > R) rows = R;
    const int n4 = rows * NF4;

    float*        sxw  = sx + w * (R * NFEAT);
    const float4* gx   = (const float4*)(x   + row0 * NFEAT);
    float4*       gout = (float4*)      (out + row0 * NFEAT);

    // sid table -> smem (all warps write identical values; benign race)
    for (int j = lane; j < 47; j += 32) sstab[j] = c_stab[j];

    // ---- phase 1: async, L1-bypassing tile load ----
    unsigned int sbase = (unsigned int)__cvta_generic_to_shared(sxw);
    #pragma unroll 3
    for (int i = lane; i < n4; i += 32) {
        asm volatile("cp.async.cg.shared.global [%0], [%1], 16;\n"
                     :: "r"(sbase + i * 16), "l"(gx + i) : "memory");
    }
    asm volatile("cp.async.commit_group;\n" ::: "memory");
    asm volatile("cp.async.wait_group 0;\n" ::: "memory");
    __syncwarp();

    // ---- phase 2: segment sums (balanced, bank-conflict-free) ----
    {
        const int rq = lane >> 2;           // row within warp tile (0..7)
        const int sq = lane & 3;            // quarter (3 segments each)
        if (rq < rows) {
            const float* xr = sxw + rq * NFEAT + sq * 47;
            float a0 = 0.f, a1 = 0.f, a2 = 0.f;
            #pragma unroll
            for (int j = 0;  j < 20; ++j) a0 += xr[j];
            #pragma unroll
            for (int j = 20; j < 26; ++j) a1 += xr[j];
            #pragma unroll
            for (int j = 26; j < 47; ++j) a2 += xr[j];
            smeans[w][rq][3 * sq + 0] = a0 * (1.f / 20.f);
            smeans[w][rq][3 * sq + 1] = a1 * (1.f / 6.f);
            smeans[w][rq][3 * sq + 2] = a2 * (1.f / 21.f);
        }
    }
    __syncwarp();

    // ---- phase 3: tiny MLP, one lane per row ----
    if (lane < rows) {
        float m[12];
        #pragma unroll
        for (int k = 0; k < 12; ++k) m[k] = smeans[w][lane][k];
        float h[3];
        #pragma unroll
        for (int j = 0; j < 3; ++j) {
            float a = __ldg(b1 + j);
            #pragma unroll
            for (int k = 0; k < 12; ++k) a += m[k] * __ldg(W1 + j * 12 + k);
            h[j] = fmaxf(a, 0.f);
        }
        #pragma unroll
        for (int s = 0; s < 12; ++s) {
            float a = __ldg(b2 + s);
            #pragma unroll
            for (int j = 0; j < 3; ++j) a += h[j] * __ldg(W2 + s * 3 + j);
            sgates[w][lane][s] = __fdividef(1.f, 1.f + __expf(-a));
        }
    }
    __syncwarp();

    // ---- phase 4: gate multiply + coalesced streaming store ----
    const float4* sxw4 = (const float4*)sxw;
    #pragma unroll 3
    for (int i = lane; i < n4; i += 32) {
        const int row = i / NF4;
        const int p   = i - row * NF4;
        const unsigned int sid = sstab[p];
        const float* gr = sgates[w][row];
        float4 v = sxw4[i];
        v.x *= gr[sid         & 255];
        v.y *= gr[(sid >> 8)  & 255];
        v.z *= gr[(sid >> 16) & 255];
        v.w *= gr[ sid >> 24       ];
        __stcs(&gout[i], v);
    }
}

extern "C" void kernel_launch(void* const* d_in, const int* in_sizes, int n_in,
                              void* d_out, int out_size)
{
    const float* x  = (const float*)d_in[0];
    const float* W1 = (const float*)d_in[1];
    const float* b1 = (const float*)d_in[2];
    const float* W2 = (const float*)d_in[3];
    const float* b2 = (const float*)d_in[4];
    float* out = (float*)d_out;

    const int B = in_sizes[0] / NFEAT;
    const int rows_per_block = WARPS * R;   // 24
    const int grid = (B + rows_per_block - 1) / rows_per_block;
    senet_kernel<<<grid, NTHREADS>>>(x, W1, b1, W2, b2, out, B);
}

// round 5
// speedup vs baseline: 1.2035x; 1.0504x over previous
#include <cuda_runtime.h>
#include <cuda_bf16.h>

// SENet gating: R2 warp-synchronous shape + cp.async.bulk (TMA path) I/O.
// Each WARP handles 8 rows (6016 B):
//   1. ONE cp.async.bulk gmem->smem (mbarrier complete_tx), warp waits
//   2. segment sums: lane (row=lane/4, quarter=lane&3) over its contiguous
//      47-float slice (pattern (20,6,21) x 4) -- balanced, conflict-free
//   3. MLP 12->3->12 (relu, sigmoid), one lane per row, weights from smem
//   4. gate-mul in place (LDS.128 -> STS.128), then ONE async bulk store
// Bulk ops keep the big traffic off the LSU wavefront path; stores drain
// asynchronously while the next block's loads begin.

#define NFEAT 188
#define NF4   47
#define R     8
#define WARPS 4
#define NTHREADS (WARPS * 32)
#define TILE_B (R * NFEAT * 4)     // 6016 bytes

// packed segment ids for the 4 features of each float4 position (0..46)
__device__ __constant__ unsigned int c_stab[47] = {
    0x00000000u,0x00000000u,0x00000000u,0x00000000u,0x00000000u,
    0x01010101u,0x02020101u,0x02020202u,0x02020202u,0x02020202u,
    0x02020202u,0x03020202u,0x03030303u,0x03030303u,0x03030303u,
    0x03030303u,0x04030303u,0x04040404u,0x05050504u,0x05050505u,
    0x05050505u,0x05050505u,0x05050505u,0x06060505u,0x06060606u,
    0x06060606u,0x06060606u,0x06060606u,0x07070606u,0x07070707u,
    0x08080808u,0x08080808u,0x08080808u,0x08080808u,0x08080808u,
    0x09090908u,0x09090909u,0x09090909u,0x09090909u,0x09090909u,
    0x0A0A0A09u,0x0B0A0A0Au,0x0B0B0B0Bu,0x0B0B0B0Bu,0x0B0B0B0Bu,
    0x0B0B0B0Bu,0x0B0B0B0Bu
};

__global__ __launch_bounds__(NTHREADS, 8)
void senet_kernel(const float* __restrict__ x,
                  const float* __restrict__ W1,   // [3,12]
                  const float* __restrict__ b1,   // [3]
                  const float* __restrict__ W2,   // [12,3]
                  const float* __restrict__ b2,   // [12]
                  float* __restrict__ out,
                  int B)
{
    __shared__ __align__(16) float sx[WARPS * R * NFEAT];   // 24064 B
    __shared__ __align__(8)  unsigned long long smbar[WARPS];
    __shared__ float        smeans[WARPS][R][12];
    __shared__ float        sgates[WARPS][R][13];
    __shared__ float        sw[WARPS][88];       // per-warp weight copy
    __shared__ unsigned int sstab[47];

    const int lane = threadIdx.x & 31;
    const int w    = threadIdx.x >> 5;

    const long long row0 = (long long)blockIdx.x * (WARPS * R) + w * R;
    int rows = B - (int)row0;
    if (rows <= 0) return;                  // warp-uniform exit
    if (rows > R) rows = R;
    const int n4    = rows * NF4;
    const unsigned int bytes = (unsigned int)n4 * 16u;

    float* sxw = sx + w * (R * NFEAT);
    const unsigned int sdst = (unsigned int)__cvta_generic_to_shared(sxw);
    const unsigned int mb   = (unsigned int)__cvta_generic_to_shared(&smbar[w]);
    const char* gsrc = (const char*)(x   + row0 * NFEAT);
    char*       gdst = (char*)      (out + row0 * NFEAT);

    // ---- phase 0: mbarrier init + launch ONE bulk load for the tile ----
    if (lane == 0) {
        asm volatile("mbarrier.init.shared.b64 [%0], 1;" :: "r"(mb) : "memory");
        asm volatile("fence.proxy.async.shared::cta;" ::: "memory");
        asm volatile("mbarrier.arrive.expect_tx.shared.b64 _, [%0], %1;"
                     :: "r"(mb), "r"(bytes) : "memory");
        asm volatile(
            "cp.async.bulk.shared::cluster.global.mbarrier::complete_tx::bytes"
            " [%0], [%1], %2, [%3];"
            :: "r"(sdst), "l"(gsrc), "r"(bytes), "r"(mb) : "memory");
    }

    // stage tables/weights while the bulk load flies
    for (int j = lane; j < 47; j += 32) sstab[j] = c_stab[j];
    for (int j = lane; j < 87; j += 32) {
        float v;
        if      (j < 36) v = __ldg(W1 + j);
        else if (j < 39) v = __ldg(b1 + (j - 36));
        else if (j < 75) v = __ldg(W2 + (j - 39));
        else             v = __ldg(b2 + (j - 75));
        sw[w][j] = v;
    }

    // ---- wait for tile (parity 0) ----
    {
        unsigned int done;
        asm volatile(
            "{\n\t.reg .pred p;\n\t"
            "mbarrier.try_wait.parity.acquire.cta.shared::cta.b64 p, [%1], 0;\n\t"
            "selp.b32 %0, 1, 0, p;\n\t}"
            : "=r"(done) : "r"(mb) : "memory");
        if (!done) {
            asm volatile(
                "{\n\t.reg .pred p;\n"
                "W_%=:\n\t"
                "mbarrier.try_wait.parity.acquire.cta.shared::cta.b64 p, [%0], 0, 0x989680;\n\t"
                "@p bra D_%=;\n\t"
                "bra.uni W_%=;\n"
                "D_%=:\n\t}"
                :: "r"(mb) : "memory");
        }
    }
    __syncwarp();

    // ---- phase 2: segment sums (balanced, bank-conflict-free) ----
    {
        const int rq = lane >> 2;
        const int sq = lane & 3;
        if (rq < rows) {
            const float* xr = sxw + rq * NFEAT + sq * 47;
            float a0 = 0.f, a1 = 0.f, a2 = 0.f;
            #pragma unroll
            for (int j = 0;  j < 20; ++j) a0 += xr[j];
            #pragma unroll
            for (int j = 20; j < 26; ++j) a1 += xr[j];
            #pragma unroll
            for (int j = 26; j < 47; ++j) a2 += xr[j];
            smeans[w][rq][3 * sq + 0] = a0 * (1.f / 20.f);
            smeans[w][rq][3 * sq + 1] = a1 * (1.f / 6.f);
            smeans[w][rq][3 * sq + 2] = a2 * (1.f / 21.f);
        }
    }
    __syncwarp();

    // ---- phase 3: tiny MLP, one lane per row ----
    if (lane < rows) {
        const float* swp = sw[w];
        float m[12];
        #pragma unroll
        for (int k = 0; k < 12; ++k) m[k] = smeans[w][lane][k];
        float h[3];
        #pragma unroll
        for (int j = 0; j < 3; ++j) {
            float a = swp[36 + j];
            #pragma unroll
            for (int k = 0; k < 12; ++k) a += m[k] * swp[j * 12 + k];
            h[j] = fmaxf(a, 0.f);
        }
        #pragma unroll
        for (int s = 0; s < 12; ++s) {
            float a = swp[75 + s];
            #pragma unroll
            for (int j = 0; j < 3; ++j) a += h[j] * swp[39 + s * 3 + j];
            sgates[w][lane][s] = __fdividef(1.f, 1.f + __expf(-a));
        }
    }
    __syncwarp();

    // ---- phase 4: gate multiply IN PLACE in smem ----
    float4* sxw4 = (float4*)sxw;
    #pragma unroll 3
    for (int i = lane; i < n4; i += 32) {
        const int row = i / NF4;
        const int p   = i - row * NF4;
        const unsigned int sid = sstab[p];
        const float* gr = sgates[w][row];
        float4 v = sxw4[i];
        v.x *= gr[sid         & 255];
        v.y *= gr[(sid >> 8)  & 255];
        v.z *= gr[(sid >> 16) & 255];
        v.w *= gr[ sid >> 24       ];
        sxw4[i] = v;
    }
    __syncwarp();

    // ---- phase 5: ONE async bulk store; drain before exit ----
    if (lane == 0) {
        asm volatile("fence.proxy.async.shared::cta;" ::: "memory");
        asm volatile(
            "cp.async.bulk.global.shared::cta.bulk_group [%0], [%1], %2;"
            :: "l"(gdst), "r"(sdst), "r"(bytes) : "memory");
        asm volatile("cp.async.bulk.commit_group;" ::: "memory");
        asm volatile("cp.async.bulk.wait_group.read 0;" ::: "memory");
    }
}

extern "C" void kernel_launch(void* const* d_in, const int* in_sizes, int n_in,
                              void* d_out, int out_size)
{
    const float* x  = (const float*)d_in[0];
    const float* W1 = (const float*)d_in[1];
    const float* b1 = (const float*)d_in[2];
    const float* W2 = (const float*)d_in[3];
    const float* b2 = (const float*)d_in[4];
    float* out = (float*)d_out;

    const int B = in_sizes[0] / NFEAT;
    const int rows_per_block = WARPS * R;   // 32
    const int grid = (B + rows_per_block - 1) / rows_per_block;
    senet_kernel<<<grid, NTHREADS>>>(x, W1, b1, W2, b2, out, B);
}

// round 7
// speedup vs baseline: 1.2171x; 1.0113x over previous
#include <cuda_runtime.h>
#include <cuda_bf16.h>

// SENet gating, block-granular TMA version (R6 + weight-staging fix).
// Each 128-thread block handles 32 rows (24064 B):
//   1. thread 0 issues ONE cp.async.bulk (24 KB) gmem->smem; every thread
//      parity-waits the same mbarrier (init covered by __syncthreads)
//   2. per-warp segment sums: lane (row=lane/4, quarter=lane&3) over its
//      contiguous 47-float slice (pattern (20,6,21) x 4) -- balanced,
//      fully unrolled, bank-conflict-free
//   3. MLP 12->3->12 (relu, sigmoid), one lane per row, weights from smem
//   4. gate-mul IN PLACE (LDS.128 -> STS.128), __syncthreads,
//      then thread 0 issues ONE 24 KB bulk store and drains it

#define NFEAT 188
#define NF4   47
#define R     8                    // rows per warp
#define WARPS 4
#define NTHREADS (WARPS * 32)
#define ROWS_BLK (WARPS * R)       // 32
#define TILE_F  (ROWS_BLK * NFEAT) // 6016 floats = 24064 B

// packed segment ids for the 4 features of each float4 position (0..46)
__device__ __constant__ unsigned int c_stab[47] = {
    0x00000000u,0x00000000u,0x00000000u,0x00000000u,0x00000000u,
    0x01010101u,0x02020101u,0x02020202u,0x02020202u,0x02020202u,
    0x02020202u,0x03020202u,0x03030303u,0x03030303u,0x03030303u,
    0x03030303u,0x04030303u,0x04040404u,0x05050504u,0x05050505u,
    0x05050505u,0x05050505u,0x05050505u,0x06060505u,0x06060606u,
    0x06060606u,0x06060606u,0x06060606u,0x07070606u,0x07070707u,
    0x08080808u,0x08080808u,0x08080808u,0x08080808u,0x08080808u,
    0x09090908u,0x09090909u,0x09090909u,0x09090909u,0x09090909u,
    0x0A0A0A09u,0x0B0A0A0Au,0x0B0B0B0Bu,0x0B0B0B0Bu,0x0B0B0B0Bu,
    0x0B0B0B0Bu,0x0B0B0B0Bu
};

__global__ __launch_bounds__(NTHREADS, 8)
void senet_kernel(const float* __restrict__ x,
                  const float* __restrict__ W1,   // [3,12]
                  const float* __restrict__ b1,   // [3]
                  const float* __restrict__ W2,   // [12,3]
                  const float* __restrict__ b2,   // [12]
                  float* __restrict__ out,
                  int B)
{
    __shared__ __align__(16) float sx[TILE_F];              // 24064 B
    __shared__ __align__(8)  unsigned long long smbar;
    __shared__ float        smeans[WARPS][R][12];
    __shared__ float        sgates[WARPS][R][13];
    __shared__ float        sw[88];
    __shared__ unsigned int sstab[47];

    const int tid  = threadIdx.x;
    const int lane = tid & 31;
    const int w    = tid >> 5;

    const long long brow0 = (long long)blockIdx.x * ROWS_BLK;
    int rows_blk = B - (int)brow0;
    if (rows_blk > ROWS_BLK) rows_blk = ROWS_BLK;
    const unsigned int bytes = (unsigned int)(rows_blk * NFEAT) * 4u;

    const unsigned int sdst = (unsigned int)__cvta_generic_to_shared(sx);
    const unsigned int mb   = (unsigned int)__cvta_generic_to_shared(&smbar);
    const char* gsrc = (const char*)(x   + brow0 * NFEAT);
    char*       gdst = (char*)      (out + brow0 * NFEAT);

    // ---- phase 0: init barrier, stage tables; ONE bulk load ----
    if (tid == 0) {
        asm volatile("mbarrier.init.shared.b64 [%0], 1;" :: "r"(mb) : "memory");
        asm volatile("fence.proxy.async.shared::cta;" ::: "memory");
        asm volatile("mbarrier.arrive.expect_tx.shared.b64 _, [%0], %1;"
                     :: "r"(mb), "r"(bytes) : "memory");
        asm volatile(
            "cp.async.bulk.shared::cluster.global.mbarrier::complete_tx::bytes"
            " [%0], [%1], %2, [%3];"
            :: "r"(sdst), "l"(gsrc), "r"(bytes), "r"(mb) : "memory");
    }
    if (tid < 47) sstab[tid] = c_stab[tid];
    // stage ALL 87 weights (fixed: full-range stride loop)
    for (int j = tid; j < 87; j += NTHREADS) {
        float v;
        if      (j < 36) v = __ldg(W1 + j);
        else if (j < 39) v = __ldg(b1 + (j - 36));
        else if (j < 75) v = __ldg(W2 + (j - 39));
        else             v = __ldg(b2 + (j - 75));
        sw[j] = v;
    }
    __syncthreads();    // mbarrier.init + tables visible to all warps

    // ---- wait for tile (parity 0), every thread ----
    {
        unsigned int done;
        asm volatile(
            "{\n\t.reg .pred p;\n\t"
            "mbarrier.try_wait.parity.acquire.cta.shared::cta.b64 p, [%1], 0;\n\t"
            "selp.b32 %0, 1, 0, p;\n\t}"
            : "=r"(done) : "r"(mb) : "memory");
        if (!done) {
            asm volatile(
                "{\n\t.reg .pred p;\n"
                "W_%=:\n\t"
                "mbarrier.try_wait.parity.acquire.cta.shared::cta.b64 p, [%0], 0, 0x989680;\n\t"
                "@p bra D_%=;\n\t"
                "bra.uni W_%=;\n"
                "D_%=:\n\t}"
                :: "r"(mb) : "memory");
        }
    }
    __syncwarp();

    // per-warp row count
    int rows = rows_blk - w * R;
    if (rows < 0) rows = 0;
    if (rows > R) rows = R;
    float* sxw = sx + w * (R * NFEAT);

    // ---- phase 2: segment sums (balanced, bank-conflict-free) ----
    {
        const int rq = lane >> 2;
        const int sq = lane & 3;
        if (rq < rows) {
            const float* xr = sxw + rq * NFEAT + sq * 47;
            float a0 = 0.f, a1 = 0.f, a2 = 0.f;
            #pragma unroll
            for (int j = 0;  j < 20; ++j) a0 += xr[j];
            #pragma unroll
            for (int j = 20; j < 26; ++j) a1 += xr[j];
            #pragma unroll
            for (int j = 26; j < 47; ++j) a2 += xr[j];
            smeans[w][rq][3 * sq + 0] = a0 * (1.f / 20.f);
            smeans[w][rq][3 * sq + 1] = a1 * (1.f / 6.f);
            smeans[w][rq][3 * sq + 2] = a2 * (1.f / 21.f);
        }
    }
    __syncwarp();

    // ---- phase 3: tiny MLP, one lane per row ----
    if (lane < rows) {
        float m[12];
        #pragma unroll
        for (int k = 0; k < 12; ++k) m[k] = smeans[w][lane][k];
        float h[3];
        #pragma unroll
        for (int j = 0; j < 3; ++j) {
            float a = sw[36 + j];
            #pragma unroll
            for (int k = 0; k < 12; ++k) a += m[k] * sw[j * 12 + k];
            h[j] = fmaxf(a, 0.f);
        }
        #pragma unroll
        for (int s = 0; s < 12; ++s) {
            float a = sw[75 + s];
            #pragma unroll
            for (int j = 0; j < 3; ++j) a += h[j] * sw[39 + s * 3 + j];
            sgates[w][lane][s] = __fdividef(1.f, 1.f + __expf(-a));
        }
    }
    __syncwarp();

    // ---- phase 4: gate multiply IN PLACE (warp's own subregion) ----
    {
        float4* sxw4 = (float4*)sxw;
        const int n4 = rows * NF4;
        #pragma unroll 3
        for (int i = lane; i < n4; i += 32) {
            const int row = i / NF4;
            const int p   = i - row * NF4;
            const unsigned int sid = sstab[p];
            const float* gr = sgates[w][row];
            float4 v = sxw4[i];
            v.x *= gr[sid         & 255];
            v.y *= gr[(sid >> 8)  & 255];
            v.z *= gr[(sid >> 16) & 255];
            v.w *= gr[ sid >> 24       ];
            sxw4[i] = v;
        }
    }
    __syncthreads();    // all warps' STS done before the bulk store

    // ---- phase 5: ONE 24 KB bulk store; drain before exit ----
    if (tid == 0) {
        asm volatile("fence.proxy.async.shared::cta;" ::: "memory");
        asm volatile(
            "cp.async.bulk.global.shared::cta.bulk_group [%0], [%1], %2;"
            :: "l"(gdst), "r"(sdst), "r"(bytes) : "memory");
        asm volatile("cp.async.bulk.commit_group;" ::: "memory");
        asm volatile("cp.async.bulk.wait_group.read 0;" ::: "memory");
    }
}

extern "C" void kernel_launch(void* const* d_in, const int* in_sizes, int n_in,
                              void* d_out, int out_size)
{
    const float* x  = (const float*)d_in[0];
    const float* W1 = (const float*)d_in[1];
    const float* b1 = (const float*)d_in[2];
    const float* W2 = (const float*)d_in[3];
    const float* b2 = (const float*)d_in[4];
    float* out = (float*)d_out;

    const int B = in_sizes[0] / NFEAT;
    const int grid = (B + ROWS_BLK - 1) / ROWS_BLK;
    senet_kernel<<<grid, NTHREADS>>>(x, W1, b1, W2, b2, out, B);
}